// round 11
// baseline (speedup 1.0000x reference)
#include <cuda_runtime.h>
#include <cuda_bf16.h>
#include <cstdint>

#define B_  32
#define D_  1024
#define T_  1024
#define H_  2048

// ---------------- scratch (device globals; allocation forbidden) ------------
__device__ float g_scores[(size_t)B_ * T_ * T_];   // qk then softmax (in place)
__device__ float g_qT   [(size_t)T_ * B_ * D_];    // [f][b*D+d]
__device__ float g_kT   [(size_t)T_ * B_ * D_];    // [f][b*D+d]
__device__ float g_attnT[(size_t)B_ * T_ * D_];    // [b][t][d]
__device__ float g_hT   [(size_t)B_ * T_ * H_];    // [b][t][h]
__device__ float g_meanv[B_ * D_];
__device__ float g_hex  [B_ * H_];

// ---------------- helpers ----------------------------------------------------
__device__ __forceinline__ uint32_t smem_u32(const void* p) {
    uint32_t a;
    asm("{ .reg .u64 t; cvta.to.shared.u64 t, %1; cvt.u32.u64 %0, t; }"
        : "=r"(a) : "l"(p));
    return a;
}

__device__ __forceinline__ void ldsm4(uint32_t* r, uint32_t a) {
    asm volatile("ldmatrix.sync.aligned.m8n8.x4.shared.b16 {%0,%1,%2,%3}, [%4];"
        : "=r"(r[0]), "=r"(r[1]), "=r"(r[2]), "=r"(r[3]) : "r"(a));
}
__device__ __forceinline__ void ldsm2(uint32_t* r, uint32_t a) {
    asm volatile("ldmatrix.sync.aligned.m8n8.x2.shared.b16 {%0,%1}, [%2];"
        : "=r"(r[0]), "=r"(r[1]) : "r"(a));
}
__device__ __forceinline__ void mma16816(float* c, const uint32_t* a, const uint32_t* b) {
    asm volatile(
        "mma.sync.aligned.m16n8k16.row.col.f32.bf16.bf16.f32 "
        "{%0,%1,%2,%3}, {%4,%5,%6,%7}, {%8,%9}, {%0,%1,%2,%3};"
        : "+f"(c[0]), "+f"(c[1]), "+f"(c[2]), "+f"(c[3])
        : "r"(a[0]), "r"(a[1]), "r"(a[2]), "r"(a[3]), "r"(b[0]), "r"(b[1]));
}

__device__ __forceinline__ uint32_t pack_bf2(__nv_bfloat16 a, __nv_bfloat16 b) {
    __nv_bfloat162 t = __halves2bfloat162(a, b);
    return *reinterpret_cast<uint32_t*>(&t);
}

// split fp32x4 -> bf16 h/m(/l) tiles at tbase, tbase+TILE, (tbase+2*TILE)
template<int NT>
__device__ __forceinline__ void split_store(char* tbase, uint32_t off, float4 v) {
    float f[4] = {v.x, v.y, v.z, v.w};
    uint32_t hw[2], mw[2], lw[2];
#pragma unroll
    for (int p = 0; p < 2; ++p) {
        __nv_bfloat16 h0 = __float2bfloat16_rn(f[2*p]);
        __nv_bfloat16 h1 = __float2bfloat16_rn(f[2*p+1]);
        float r0 = f[2*p]   - __bfloat162float(h0);
        float r1 = f[2*p+1] - __bfloat162float(h1);
        __nv_bfloat16 m0 = __float2bfloat16_rn(r0);
        __nv_bfloat16 m1 = __float2bfloat16_rn(r1);
        hw[p] = pack_bf2(h0, h1);
        mw[p] = pack_bf2(m0, m1);
        if (NT == 3) {
            r0 -= __bfloat162float(m0);
            r1 -= __bfloat162float(m1);
            lw[p] = pack_bf2(__float2bfloat16_rn(r0), __float2bfloat16_rn(r1));
        }
    }
    *(uint2*)(tbase + off)         = make_uint2(hw[0], hw[1]);
    *(uint2*)(tbase + 10240 + off) = make_uint2(mw[0], mw[1]);
    if (NT == 3)
        *(uint2*)(tbase + 20480 + off) = make_uint2(lw[0], lw[1]);
}

// ---------------------------------------------------------------------------
// mma.sync split GEMM: C[m,n] = sum_k A[m,k]*B[n,k] (+bias)(+relu)
// A [M,K] k-major (lda), B [N,K] k-major (ldb). Tile 128x128, BK=32 fp32.
// PASSES: 3 (h,m split ~2^-18) or 6 (h,m,l split ~2^-23).
// OUTT: 0 natural only, 1 both, 2 transposed only. CT[n][m] leading dim ldt.
// BIAS: 0 none, 1 over n, 2 over m.
// smem tile: 128 rows x 80B (32 bf16 data + pad) -> conflict-free ldmatrix.
// ---------------------------------------------------------------------------
template<int PASSES, int BIAS, bool RELU, int OUTT>
__global__ __launch_bounds__(256, 2)
void mgemm(const float* __restrict__ A, long long sA, int lda,
           const float* __restrict__ Bp, long long sB, int ldb,
           float* __restrict__ C, long long sC, int ldc,
           float* __restrict__ CT, long long sCT, int ldt,
           const float* __restrict__ bias, int Kdim)
{
    constexpr int NT   = (PASSES == 6) ? 3 : 2;
    constexpr int TILE = 10240;                 // 128 * 80 bytes
    extern __shared__ char sm[];
    char* smA = sm;
    char* smB = sm + NT * TILE;
    const uint32_t uA = smem_u32(smA);
    const uint32_t uB = smem_u32(smB);

    const int tid = threadIdx.x, lane = tid & 31, wid = tid >> 5;
    const int wm = wid & 1, wn = wid >> 1;      // warp grid 2(m) x 4(n)
    const int m0 = blockIdx.y * 128, n0 = blockIdx.x * 128, z = blockIdx.z;
    const float* Ab = A  + (size_t)z * sA;
    const float* Bb = Bp + (size_t)z * sB;

    float acc[4][4][4];
#pragma unroll
    for (int i = 0; i < 4; ++i)
#pragma unroll
        for (int j = 0; j < 4; ++j)
#pragma unroll
            for (int c = 0; c < 4; ++c) acc[i][j][c] = 0.f;

    const int r8 = tid >> 3;                    // 0..31
    const int c4 = (tid & 7) << 2;              // fp32 col 0,4,..,28

    // per-thread ldmatrix row addresses
    const uint32_t aRow = (uint32_t)((wm * 64 + (lane & 15)) * 80 + (lane >> 4) * 16);
    const uint32_t bRow = (uint32_t)((wn * 32 + (lane & 7)) * 80 + ((lane >> 3) & 1) * 16);

    // pass -> (A tile, B tile); first 3 entries are the 3-pass schedule
    constexpr int PA[6] = {0, 0, 1, 0, 2, 1};
    constexpr int PB[6] = {0, 1, 0, 2, 0, 1};

    for (int k0 = 0; k0 < Kdim; k0 += 32) {
#pragma unroll
        for (int i = 0; i < 4; ++i) {
            const int row = i * 32 + r8;
            const uint32_t off = (uint32_t)(row * 80 + c4 * 2);
            float4 va = *(const float4*)(Ab + (size_t)(m0 + row) * lda + k0 + c4);
            split_store<NT>(smA, off, va);
            float4 vb = *(const float4*)(Bb + (size_t)(n0 + row) * ldb + k0 + c4);
            split_store<NT>(smB, off, vb);
        }
        __syncthreads();

#pragma unroll
        for (int p = 0; p < PASSES; ++p) {
            const uint32_t aBase = uA + PA[p] * TILE + aRow;
            const uint32_t bBase = uB + PB[p] * TILE + bRow;
#pragma unroll
            for (int ks = 0; ks < 2; ++ks) {
                uint32_t af[4][4], bf[4][2];
#pragma unroll
                for (int mt = 0; mt < 4; ++mt)
                    ldsm4(af[mt], aBase + mt * (16 * 80) + ks * 32);
#pragma unroll
                for (int nt = 0; nt < 4; ++nt)
                    ldsm2(bf[nt], bBase + nt * (8 * 80) + ks * 32);
#pragma unroll
                for (int mt = 0; mt < 4; ++mt)
#pragma unroll
                    for (int nt = 0; nt < 4; ++nt)
                        mma16816(acc[mt][nt], af[mt], bf[nt]);
            }
        }
        __syncthreads();
    }

    // ---- epilogue (direct from fragments) ----
    const int mBase = m0 + wm * 64;
    const int nBase = n0 + wn * 32;
    const int rq = lane >> 2;          // 0..7
    const int cq = (lane & 3) * 2;     // 0,2,4,6

    if (OUTT != 2) {
        float* Cb = C + (size_t)z * sC;
#pragma unroll
        for (int mt = 0; mt < 4; ++mt) {
#pragma unroll
            for (int nt = 0; nt < 4; ++nt) {
                const int m = mBase + mt * 16 + rq;
                const int n = nBase + nt * 8 + cq;
                float x0 = acc[mt][nt][0], x1 = acc[mt][nt][1];
                float x2 = acc[mt][nt][2], x3 = acc[mt][nt][3];
                if (BIAS == 1) {
                    float b0 = bias[n], b1 = bias[n + 1];
                    x0 += b0; x1 += b1; x2 += b0; x3 += b1;
                }
                if (BIAS == 2) {
                    float bm0 = bias[m], bm1 = bias[m + 8];
                    x0 += bm0; x1 += bm0; x2 += bm1; x3 += bm1;
                }
                if (RELU) {
                    x0 = fmaxf(x0, 0.f); x1 = fmaxf(x1, 0.f);
                    x2 = fmaxf(x2, 0.f); x3 = fmaxf(x3, 0.f);
                }
                if ((ldc & 1) == 0) {
                    *(float2*)(Cb + (size_t)m * ldc + n)       = make_float2(x0, x1);
                    *(float2*)(Cb + (size_t)(m + 8) * ldc + n) = make_float2(x2, x3);
                } else {
                    Cb[(size_t)m * ldc + n]           = x0;
                    Cb[(size_t)m * ldc + n + 1]       = x1;
                    Cb[(size_t)(m + 8) * ldc + n]     = x2;
                    Cb[(size_t)(m + 8) * ldc + n + 1] = x3;
                }
            }
        }
    }

    if (OUTT != 0) {
        float* Tb = CT + (size_t)z * sCT;
#pragma unroll
        for (int mt = 0; mt < 4; ++mt) {
#pragma unroll
            for (int nt = 0; nt < 4; ++nt) {
                const int m = mBase + mt * 16 + rq;
                const int n = nBase + nt * 8 + cq;
                float x0 = acc[mt][nt][0], x1 = acc[mt][nt][1];
                float x2 = acc[mt][nt][2], x3 = acc[mt][nt][3];
                if (BIAS == 1) {
                    float b0 = bias[n], b1 = bias[n + 1];
                    x0 += b0; x1 += b1; x2 += b0; x3 += b1;
                }
                if (BIAS == 2) {
                    float bm0 = bias[m], bm1 = bias[m + 8];
                    x0 += bm0; x1 += bm0; x2 += bm1; x3 += bm1;
                }
                if (RELU) {
                    x0 = fmaxf(x0, 0.f); x1 = fmaxf(x1, 0.f);
                    x2 = fmaxf(x2, 0.f); x3 = fmaxf(x3, 0.f);
                }
                Tb[(size_t)n * ldt + m]           = x0;
                Tb[(size_t)(n + 1) * ldt + m]     = x1;
                Tb[(size_t)n * ldt + m + 8]       = x2;
                Tb[(size_t)(n + 1) * ldt + m + 8] = x3;
            }
        }
    }
}

// ---------------------------------------------------------------------------
// Double-exp softmax, exactly mirroring JAX (in place)
// ---------------------------------------------------------------------------
__global__ void softmax_dexp(float* __restrict__ S)
{
    const int i = blockIdx.x;
    float* row = S + ((size_t)blockIdx.y * T_ + i) * T_;
    __shared__ float buf[T_];
    __shared__ float red[9];
    const int tid = threadIdx.x;  // 256

    float lmax = -3.402823466e38f;
    for (int j = tid; j < T_; j += 256) {
        float x = row[j];
        if (j == i) x *= 0.96875f;   // 1 - 1/sqrt(1024), exact
        float e = expf(x);
        buf[j] = e;
        lmax = fmaxf(lmax, e);
    }
#pragma unroll
    for (int o = 16; o; o >>= 1) lmax = fmaxf(lmax, __shfl_xor_sync(0xffffffffu, lmax, o));
    if ((tid & 31) == 0) red[tid >> 5] = lmax;
    __syncthreads();
    if (tid == 0) {
        float m = red[0];
        for (int s = 1; s < 8; ++s) m = fmaxf(m, red[s]);
        red[8] = m;
    }
    __syncthreads();
    const float M = red[8];

    float ls = 0.f;
    for (int j = tid; j < T_; j += 256) {
        float t = expf(buf[j] - M);
        buf[j] = t;
        ls += t;
    }
#pragma unroll
    for (int o = 16; o; o >>= 1) ls += __shfl_xor_sync(0xffffffffu, ls, o);
    if ((tid & 31) == 0) red[tid >> 5] = ls;
    __syncthreads();
    if (tid == 0) {
        float s = 0.f;
        for (int t = 0; t < 8; ++t) s += red[t];
        red[8] = 1.0f / s;
    }
    __syncthreads();
    const float inv = red[8];
    for (int j = tid; j < T_; j += 256) row[j] = buf[j] * inv;
}

// ---------------------------------------------------------------------------
__device__ __forceinline__ float warp_sum(float v)
{
#pragma unroll
    for (int o = 16; o; o >>= 1) v += __shfl_xor_sync(0xffffffffu, v, o);
    return v;
}

__global__ void meanv_k(const float* __restrict__ V, float* __restrict__ out)
{
    const int w = (blockIdx.x * blockDim.x + threadIdx.x) >> 5;
    const int lane = threadIdx.x & 31;
    if (w >= B_ * D_) return;
    const float* r = V + (size_t)w * T_;
    float s = 0.f;
    for (int j = 25 + lane; j < 1023; j += 32) s += r[j];
    s = warp_sum(s);
    if (lane == 0) out[w] = s * (1.0f / 998.0f);
}

__global__ void hex_k(const float* __restrict__ W1, const float* __restrict__ b1,
                      const float* __restrict__ mv, float* __restrict__ hx)
{
    const int w = (blockIdx.x * blockDim.x + threadIdx.x) >> 5;
    const int lane = threadIdx.x & 31;
    if (w >= B_ * H_) return;
    const int b = w >> 11, h = w & (H_ - 1);
    const float* wr = W1 + (size_t)h * D_;
    const float* xr = mv + (size_t)b * D_;
    float s = 0.f;
    for (int d = lane; d < D_; d += 32) s += wr[d] * xr[d];
    s = warp_sum(s);
    if (lane == 0) hx[w] = fmaxf(s + b1[h], 0.f);
}

__global__ void yex_k(const float* __restrict__ W2, const float* __restrict__ b2,
                      const float* __restrict__ hx, float* __restrict__ rep)
{
    const int w = (blockIdx.x * blockDim.x + threadIdx.x) >> 5;
    const int lane = threadIdx.x & 31;
    if (w >= B_ * D_) return;
    const int b = w >> 10, d = w & (D_ - 1);
    const float* wr = W2 + (size_t)d * H_;
    const float* xr = hx + (size_t)b * H_;
    float s = 0.f;
    for (int h = lane; h < H_; h += 32) s += wr[h] * xr[h];
    s = warp_sum(s);
    if (lane == 0) rep[((size_t)b * D_ + d) * 1025 + 1024] = s + b2[d];
}

// ---------------------------------------------------------------------------
extern "C" void kernel_launch(void* const* d_in, const int* in_sizes, int n_in,
                              void* d_out, int out_size)
{
    const float* pattern = (const float*)d_in[0];
    const float* value   = (const float*)d_in[1];
    const float* Wq      = (const float*)d_in[2];
    const float* bq      = (const float*)d_in[3];
    const float* Wk      = (const float*)d_in[4];
    const float* bk      = (const float*)d_in[5];
    const float* W1      = (const float*)d_in[6];
    const float* b1      = (const float*)d_in[7];
    const float* W2      = (const float*)d_in[8];
    const float* b2      = (const float*)d_in[9];

    float* out = (float*)d_out;
    float* rep = out;                                   // (B, D, 1025)
    float* q   = out + (size_t)B_ * D_ * 1025;          // (B, D, T)
    float* k   = q   + (size_t)B_ * D_ * T_;            // (B, D, T)

    float *scores, *qT, *kT, *attnT, *hT, *mv, *hx;
    cudaGetSymbolAddress((void**)&scores, g_scores);
    cudaGetSymbolAddress((void**)&qT,     g_qT);
    cudaGetSymbolAddress((void**)&kT,     g_kT);
    cudaGetSymbolAddress((void**)&attnT,  g_attnT);
    cudaGetSymbolAddress((void**)&hT,     g_hT);
    cudaGetSymbolAddress((void**)&mv,     g_meanv);
    cudaGetSymbolAddress((void**)&hx,     g_hex);

    const int SM6 = 6 * 10240;   // 61440
    const int SM3 = 4 * 10240;   // 40960
    cudaFuncSetAttribute(mgemm<6,1,false,1>, cudaFuncAttributeMaxDynamicSharedMemorySize, SM6);
    cudaFuncSetAttribute(mgemm<6,0,false,0>, cudaFuncAttributeMaxDynamicSharedMemorySize, SM6);
    cudaFuncSetAttribute(mgemm<3,0,false,0>, cudaFuncAttributeMaxDynamicSharedMemorySize, SM3);
    cudaFuncSetAttribute(mgemm<3,2,true ,2>, cudaFuncAttributeMaxDynamicSharedMemorySize, SM3);
    cudaFuncSetAttribute(mgemm<3,2,false,0>, cudaFuncAttributeMaxDynamicSharedMemorySize, SM3);

    // 1) q/k projections (6-pass): natural into d_out + transposed scratch
    //    M=32768 (b*D+d), N=1024 (f), K=1024 (t)
    mgemm<6,1,false,1><<<dim3(8, 256, 1), 256, SM6>>>(
        pattern, 0, T_, Wq, 0, T_, q, 0, T_, qT, 0, B_ * D_, bq, T_);
    mgemm<6,1,false,1><<<dim3(8, 256, 1), 256, SM6>>>(
        pattern, 0, T_, Wk, 0, T_, k, 0, T_, kT, 0, B_ * D_, bk, T_);

    // 2) qk[b,i,j] = sum_d qT[i][bD+d] * kT[j][bD+d]  (6-pass, batched)
    mgemm<6,0,false,0><<<dim3(8, 8, B_), 256, SM6>>>(
        qT, D_, B_ * D_, kT, D_, B_ * D_,
        scores, (long long)T_ * T_, T_, nullptr, 0, 0, nullptr, D_);

    // 3) double-exp softmax (in place)
    softmax_dexp<<<dim3(T_, B_), 256>>>(scores);

    // 4) attnT[b,t,d] = sum_j scores[b,t,j] * value[b,d,j]  (3-pass, natural out)
    mgemm<3,0,false,0><<<dim3(8, 8, B_), 256, SM3>>>(
        scores, (long long)T_ * T_, T_, value, (long long)D_ * T_, T_,
        attnT, (long long)T_ * D_, D_, nullptr, 0, 0, nullptr, T_);

    // 5) hT[b,t,h] = relu(W1[h,:] . attnT[b,t,:] + b1[h])  (3-pass, transposed out)
    mgemm<3,2,true,2><<<dim3(8, 16, B_), 256, SM3>>>(
        W1, 0, D_, attnT, (long long)T_ * D_, D_,
        nullptr, 0, 0, hT, (long long)T_ * H_, H_, b1, D_);

    // 6) rep_in[b,d,t] = W2[d,:] . hT[b,t,:] + b2[d]  (3-pass), ldc=1025
    mgemm<3,2,false,0><<<dim3(8, 8, B_), 256, SM3>>>(
        W2, 0, H_, hT, (long long)T_ * H_, H_,
        rep, (long long)D_ * 1025, 1025, nullptr, 0, 0, b2, H_);

    // 7) ex branch: uniform attention => row-mean of value, tiny MLP
    meanv_k<<<4096, 256>>>(value, mv);
    hex_k<<<8192, 256>>>(W1, b1, mv, hx);
    yex_k<<<4096, 256>>>(W2, b2, hx, rep);
}

// round 12
// speedup vs baseline: 1.0271x; 1.0271x over previous
#include <cuda_runtime.h>
#include <cuda_bf16.h>
#include <cstdint>

#define B_  32
#define D_  1024
#define T_  1024
#define H_  2048

// ---------------- scratch (device globals; allocation forbidden) ------------
__device__ float g_scores[(size_t)B_ * T_ * T_];   // qk then softmax (in place)
__device__ float g_qT   [(size_t)T_ * B_ * D_];    // [f][b*D+d]
__device__ float g_kT   [(size_t)T_ * B_ * D_];    // [f][b*D+d]
__device__ float g_attnT[(size_t)B_ * T_ * D_];    // [b][t][d]
__device__ float g_hT   [(size_t)B_ * T_ * H_];    // [b][t][h]
__device__ float g_meanv[B_ * D_];
__device__ float g_hex  [B_ * H_];

// ---------------- helpers ----------------------------------------------------
__device__ __forceinline__ uint32_t smem_u32(const void* p) {
    uint32_t a;
    asm("{ .reg .u64 t; cvta.to.shared.u64 t, %1; cvt.u32.u64 %0, t; }"
        : "=r"(a) : "l"(p));
    return a;
}

__device__ __forceinline__ void ldsm4(uint32_t* r, uint32_t a) {
    asm volatile("ldmatrix.sync.aligned.m8n8.x4.shared.b16 {%0,%1,%2,%3}, [%4];"
        : "=r"(r[0]), "=r"(r[1]), "=r"(r[2]), "=r"(r[3]) : "r"(a));
}
__device__ __forceinline__ void ldsm2(uint32_t* r, uint32_t a) {
    asm volatile("ldmatrix.sync.aligned.m8n8.x2.shared.b16 {%0,%1}, [%2];"
        : "=r"(r[0]), "=r"(r[1]) : "r"(a));
}
__device__ __forceinline__ void mma16816(float* c, const uint32_t* a, const uint32_t* b) {
    asm volatile(
        "mma.sync.aligned.m16n8k16.row.col.f32.bf16.bf16.f32 "
        "{%0,%1,%2,%3}, {%4,%5,%6,%7}, {%8,%9}, {%0,%1,%2,%3};"
        : "+f"(c[0]), "+f"(c[1]), "+f"(c[2]), "+f"(c[3])
        : "r"(a[0]), "r"(a[1]), "r"(a[2]), "r"(a[3]), "r"(b[0]), "r"(b[1]));
}

__device__ __forceinline__ uint32_t pack_bf2(__nv_bfloat16 a, __nv_bfloat16 b) {
    __nv_bfloat162 t = __halves2bfloat162(a, b);
    return *reinterpret_cast<uint32_t*>(&t);
}

// split fp32x4 -> bf16 h/m(/l) tiles at tbase, tbase+TILE, (tbase+2*TILE)
template<int NT>
__device__ __forceinline__ void split_store(char* tbase, uint32_t off, float4 v) {
    float f[4] = {v.x, v.y, v.z, v.w};
    uint32_t hw[2], mw[2], lw[2];
#pragma unroll
    for (int p = 0; p < 2; ++p) {
        __nv_bfloat16 h0 = __float2bfloat16_rn(f[2*p]);
        __nv_bfloat16 h1 = __float2bfloat16_rn(f[2*p+1]);
        float r0 = f[2*p]   - __bfloat162float(h0);
        float r1 = f[2*p+1] - __bfloat162float(h1);
        __nv_bfloat16 m0 = __float2bfloat16_rn(r0);
        __nv_bfloat16 m1 = __float2bfloat16_rn(r1);
        hw[p] = pack_bf2(h0, h1);
        mw[p] = pack_bf2(m0, m1);
        if (NT == 3) {
            r0 -= __bfloat162float(m0);
            r1 -= __bfloat162float(m1);
            lw[p] = pack_bf2(__float2bfloat16_rn(r0), __float2bfloat16_rn(r1));
        }
    }
    *(uint2*)(tbase + off)         = make_uint2(hw[0], hw[1]);
    *(uint2*)(tbase + 10240 + off) = make_uint2(mw[0], mw[1]);
    if (NT == 3)
        *(uint2*)(tbase + 20480 + off) = make_uint2(lw[0], lw[1]);
}

// ---------------------------------------------------------------------------
// mma.sync split GEMM: C[m,n] = sum_k A[m,k]*B[n,k] (+bias)(+relu)
// A [M,K] k-major (lda), B [N,K] k-major (ldb). Tile 128x128, BK=32 fp32.
// PASSES: 3 (h,m split ~2^-18) or 6 (h,m,l split ~2^-23).
// OUTT: 0 natural only, 1 both, 2 transposed only. CT[n][m] leading dim ldt.
// BIAS: 0 none, 1 over n, 2 over m.
// smem tile: 128 rows x 80B (32 bf16 data + pad) -> conflict-free ldmatrix.
// ---------------------------------------------------------------------------
template<int PASSES, int BIAS, bool RELU, int OUTT>
__global__ __launch_bounds__(256, 2)
void mgemm(const float* __restrict__ A, long long sA, int lda,
           const float* __restrict__ Bp, long long sB, int ldb,
           float* __restrict__ C, long long sC, int ldc,
           float* __restrict__ CT, long long sCT, int ldt,
           const float* __restrict__ bias, int Kdim)
{
    constexpr int NT   = (PASSES == 6) ? 3 : 2;
    constexpr int TILE = 10240;                 // 128 * 80 bytes
    extern __shared__ char sm[];
    char* smA = sm;
    char* smB = sm + NT * TILE;
    const uint32_t uA = smem_u32(smA);
    const uint32_t uB = smem_u32(smB);

    const int tid = threadIdx.x, lane = tid & 31, wid = tid >> 5;
    const int wm = wid & 1, wn = wid >> 1;      // warp grid 2(m) x 4(n)
    const int m0 = blockIdx.y * 128, n0 = blockIdx.x * 128, z = blockIdx.z;
    const float* Ab = A  + (size_t)z * sA;
    const float* Bb = Bp + (size_t)z * sB;

    float acc[4][4][4];
#pragma unroll
    for (int i = 0; i < 4; ++i)
#pragma unroll
        for (int j = 0; j < 4; ++j)
#pragma unroll
            for (int c = 0; c < 4; ++c) acc[i][j][c] = 0.f;

    const int r8 = tid >> 3;                    // 0..31
    const int c4 = (tid & 7) << 2;              // fp32 col 0,4,..,28

    // per-thread ldmatrix row addresses
    const uint32_t aRow = (uint32_t)((wm * 64 + (lane & 15)) * 80 + (lane >> 4) * 16);
    const uint32_t bRow = (uint32_t)((wn * 32 + (lane & 7)) * 80 + ((lane >> 3) & 1) * 16);

    // pass -> (A tile, B tile); first 3 entries are the 3-pass schedule
    constexpr int PA[6] = {0, 0, 1, 0, 2, 1};
    constexpr int PB[6] = {0, 1, 0, 2, 0, 1};

    for (int k0 = 0; k0 < Kdim; k0 += 32) {
#pragma unroll
        for (int i = 0; i < 4; ++i) {
            const int row = i * 32 + r8;
            const uint32_t off = (uint32_t)(row * 80 + c4 * 2);
            float4 va = *(const float4*)(Ab + (size_t)(m0 + row) * lda + k0 + c4);
            split_store<NT>(smA, off, va);
            float4 vb = *(const float4*)(Bb + (size_t)(n0 + row) * ldb + k0 + c4);
            split_store<NT>(smB, off, vb);
        }
        __syncthreads();

#pragma unroll
        for (int p = 0; p < PASSES; ++p) {
            const uint32_t aBase = uA + PA[p] * TILE + aRow;
            const uint32_t bBase = uB + PB[p] * TILE + bRow;
#pragma unroll
            for (int ks = 0; ks < 2; ++ks) {
                uint32_t af[4][4], bf[4][2];
#pragma unroll
                for (int mt = 0; mt < 4; ++mt)
                    ldsm4(af[mt], aBase + mt * (16 * 80) + ks * 32);
#pragma unroll
                for (int nt = 0; nt < 4; ++nt)
                    ldsm2(bf[nt], bBase + nt * (8 * 80) + ks * 32);
#pragma unroll
                for (int mt = 0; mt < 4; ++mt)
#pragma unroll
                    for (int nt = 0; nt < 4; ++nt)
                        mma16816(acc[mt][nt], af[mt], bf[nt]);
            }
        }
        __syncthreads();
    }

    // ---- epilogue (direct from fragments) ----
    const int mBase = m0 + wm * 64;
    const int nBase = n0 + wn * 32;
    const int rq = lane >> 2;          // 0..7
    const int cq = (lane & 3) * 2;     // 0,2,4,6

    if (OUTT != 2) {
        float* Cb = C + (size_t)z * sC;
#pragma unroll
        for (int mt = 0; mt < 4; ++mt) {
#pragma unroll
            for (int nt = 0; nt < 4; ++nt) {
                const int m = mBase + mt * 16 + rq;
                const int n = nBase + nt * 8 + cq;
                float x0 = acc[mt][nt][0], x1 = acc[mt][nt][1];
                float x2 = acc[mt][nt][2], x3 = acc[mt][nt][3];
                if (BIAS == 1) {
                    float b0 = bias[n], b1 = bias[n + 1];
                    x0 += b0; x1 += b1; x2 += b0; x3 += b1;
                }
                if (BIAS == 2) {
                    float bm0 = bias[m], bm1 = bias[m + 8];
                    x0 += bm0; x1 += bm0; x2 += bm1; x3 += bm1;
                }
                if (RELU) {
                    x0 = fmaxf(x0, 0.f); x1 = fmaxf(x1, 0.f);
                    x2 = fmaxf(x2, 0.f); x3 = fmaxf(x3, 0.f);
                }
                if ((ldc & 1) == 0) {
                    *(float2*)(Cb + (size_t)m * ldc + n)       = make_float2(x0, x1);
                    *(float2*)(Cb + (size_t)(m + 8) * ldc + n) = make_float2(x2, x3);
                } else {
                    Cb[(size_t)m * ldc + n]           = x0;
                    Cb[(size_t)m * ldc + n + 1]       = x1;
                    Cb[(size_t)(m + 8) * ldc + n]     = x2;
                    Cb[(size_t)(m + 8) * ldc + n + 1] = x3;
                }
            }
        }
    }

    if (OUTT != 0) {
        float* Tb = CT + (size_t)z * sCT;
#pragma unroll
        for (int mt = 0; mt < 4; ++mt) {
#pragma unroll
            for (int nt = 0; nt < 4; ++nt) {
                const int m = mBase + mt * 16 + rq;
                const int n = nBase + nt * 8 + cq;
                float x0 = acc[mt][nt][0], x1 = acc[mt][nt][1];
                float x2 = acc[mt][nt][2], x3 = acc[mt][nt][3];
                if (BIAS == 1) {
                    float b0 = bias[n], b1 = bias[n + 1];
                    x0 += b0; x1 += b1; x2 += b0; x3 += b1;
                }
                if (BIAS == 2) {
                    float bm0 = bias[m], bm1 = bias[m + 8];
                    x0 += bm0; x1 += bm0; x2 += bm1; x3 += bm1;
                }
                if (RELU) {
                    x0 = fmaxf(x0, 0.f); x1 = fmaxf(x1, 0.f);
                    x2 = fmaxf(x2, 0.f); x3 = fmaxf(x3, 0.f);
                }
                Tb[(size_t)n * ldt + m]           = x0;
                Tb[(size_t)(n + 1) * ldt + m]     = x1;
                Tb[(size_t)n * ldt + m + 8]       = x2;
                Tb[(size_t)(n + 1) * ldt + m + 8] = x3;
            }
        }
    }
}

// ---------------------------------------------------------------------------
// Double-exp softmax, exactly mirroring JAX (in place)
// ---------------------------------------------------------------------------
__global__ void softmax_dexp(float* __restrict__ S)
{
    const int i = blockIdx.x;
    float* row = S + ((size_t)blockIdx.y * T_ + i) * T_;
    __shared__ float buf[T_];
    __shared__ float red[9];
    const int tid = threadIdx.x;  // 256

    float lmax = -3.402823466e38f;
    for (int j = tid; j < T_; j += 256) {
        float x = row[j];
        if (j == i) x *= 0.96875f;   // 1 - 1/sqrt(1024), exact
        float e = expf(x);
        buf[j] = e;
        lmax = fmaxf(lmax, e);
    }
#pragma unroll
    for (int o = 16; o; o >>= 1) lmax = fmaxf(lmax, __shfl_xor_sync(0xffffffffu, lmax, o));
    if ((tid & 31) == 0) red[tid >> 5] = lmax;
    __syncthreads();
    if (tid == 0) {
        float m = red[0];
        for (int s = 1; s < 8; ++s) m = fmaxf(m, red[s]);
        red[8] = m;
    }
    __syncthreads();
    const float M = red[8];

    float ls = 0.f;
    for (int j = tid; j < T_; j += 256) {
        float t = expf(buf[j] - M);
        buf[j] = t;
        ls += t;
    }
#pragma unroll
    for (int o = 16; o; o >>= 1) ls += __shfl_xor_sync(0xffffffffu, ls, o);
    if ((tid & 31) == 0) red[tid >> 5] = ls;
    __syncthreads();
    if (tid == 0) {
        float s = 0.f;
        for (int t = 0; t < 8; ++t) s += red[t];
        red[8] = 1.0f / s;
    }
    __syncthreads();
    const float inv = red[8];
    for (int j = tid; j < T_; j += 256) row[j] = buf[j] * inv;
}

// ---------------------------------------------------------------------------
__device__ __forceinline__ float warp_sum(float v)
{
#pragma unroll
    for (int o = 16; o; o >>= 1) v += __shfl_xor_sync(0xffffffffu, v, o);
    return v;
}

__global__ void meanv_k(const float* __restrict__ V, float* __restrict__ out)
{
    const int w = (blockIdx.x * blockDim.x + threadIdx.x) >> 5;
    const int lane = threadIdx.x & 31;
    if (w >= B_ * D_) return;
    const float* r = V + (size_t)w * T_;
    float s = 0.f;
    for (int j = 25 + lane; j < 1023; j += 32) s += r[j];
    s = warp_sum(s);
    if (lane == 0) out[w] = s * (1.0f / 998.0f);
}

__global__ void hex_k(const float* __restrict__ W1, const float* __restrict__ b1,
                      const float* __restrict__ mv, float* __restrict__ hx)
{
    const int w = (blockIdx.x * blockDim.x + threadIdx.x) >> 5;
    const int lane = threadIdx.x & 31;
    if (w >= B_ * H_) return;
    const int b = w >> 11, h = w & (H_ - 1);
    const float* wr = W1 + (size_t)h * D_;
    const float* xr = mv + (size_t)b * D_;
    float s = 0.f;
    for (int d = lane; d < D_; d += 32) s += wr[d] * xr[d];
    s = warp_sum(s);
    if (lane == 0) hx[w] = fmaxf(s + b1[h], 0.f);
}

__global__ void yex_k(const float* __restrict__ W2, const float* __restrict__ b2,
                      const float* __restrict__ hx, float* __restrict__ rep)
{
    const int w = (blockIdx.x * blockDim.x + threadIdx.x) >> 5;
    const int lane = threadIdx.x & 31;
    if (w >= B_ * D_) return;
    const int b = w >> 10, d = w & (D_ - 1);
    const float* wr = W2 + (size_t)d * H_;
    const float* xr = hx + (size_t)b * H_;
    float s = 0.f;
    for (int h = lane; h < H_; h += 32) s += wr[h] * xr[h];
    s = warp_sum(s);
    if (lane == 0) rep[((size_t)b * D_ + d) * 1025 + 1024] = s + b2[d];
}

// ---------------------------------------------------------------------------
extern "C" void kernel_launch(void* const* d_in, const int* in_sizes, int n_in,
                              void* d_out, int out_size)
{
    const float* pattern = (const float*)d_in[0];
    const float* value   = (const float*)d_in[1];
    const float* Wq      = (const float*)d_in[2];
    const float* bq      = (const float*)d_in[3];
    const float* Wk      = (const float*)d_in[4];
    const float* bk      = (const float*)d_in[5];
    const float* W1      = (const float*)d_in[6];
    const float* b1      = (const float*)d_in[7];
    const float* W2      = (const float*)d_in[8];
    const float* b2      = (const float*)d_in[9];

    float* out = (float*)d_out;
    float* rep = out;                                   // (B, D, 1025)
    float* q   = out + (size_t)B_ * D_ * 1025;          // (B, D, T)
    float* k   = q   + (size_t)B_ * D_ * T_;            // (B, D, T)

    float *scores, *qT, *kT, *attnT, *hT, *mv, *hx;
    cudaGetSymbolAddress((void**)&scores, g_scores);
    cudaGetSymbolAddress((void**)&qT,     g_qT);
    cudaGetSymbolAddress((void**)&kT,     g_kT);
    cudaGetSymbolAddress((void**)&attnT,  g_attnT);
    cudaGetSymbolAddress((void**)&hT,     g_hT);
    cudaGetSymbolAddress((void**)&mv,     g_meanv);
    cudaGetSymbolAddress((void**)&hx,     g_hex);

    const int SM6 = 6 * 10240;   // 61440
    const int SM3 = 4 * 10240;   // 40960
    cudaFuncSetAttribute(mgemm<6,1,false,1>, cudaFuncAttributeMaxDynamicSharedMemorySize, SM6);
    cudaFuncSetAttribute(mgemm<6,0,false,0>, cudaFuncAttributeMaxDynamicSharedMemorySize, SM6);
    cudaFuncSetAttribute(mgemm<3,0,false,0>, cudaFuncAttributeMaxDynamicSharedMemorySize, SM3);
    cudaFuncSetAttribute(mgemm<3,2,true ,2>, cudaFuncAttributeMaxDynamicSharedMemorySize, SM3);
    cudaFuncSetAttribute(mgemm<3,2,false,0>, cudaFuncAttributeMaxDynamicSharedMemorySize, SM3);

    // 1) q/k projections (6-pass): natural into d_out + transposed scratch
    //    M=32768 (b*D+d), N=1024 (f), K=1024 (t)
    mgemm<6,1,false,1><<<dim3(8, 256, 1), 256, SM6>>>(
        pattern, 0, T_, Wq, 0, T_, q, 0, T_, qT, 0, B_ * D_, bq, T_);
    mgemm<6,1,false,1><<<dim3(8, 256, 1), 256, SM6>>>(
        pattern, 0, T_, Wk, 0, T_, k, 0, T_, kT, 0, B_ * D_, bk, T_);

    // 2) qk[b,i,j] = sum_d qT[i][bD+d] * kT[j][bD+d]  (6-pass, batched)
    mgemm<6,0,false,0><<<dim3(8, 8, B_), 256, SM6>>>(
        qT, D_, B_ * D_, kT, D_, B_ * D_,
        scores, (long long)T_ * T_, T_, nullptr, 0, 0, nullptr, D_);

    // 3) double-exp softmax (in place)
    softmax_dexp<<<dim3(T_, B_), 256>>>(scores);

    // 4) attnT[b,t,d] = sum_j scores[b,t,j] * value[b,d,j]  (3-pass, natural out)
    mgemm<3,0,false,0><<<dim3(8, 8, B_), 256, SM3>>>(
        scores, (long long)T_ * T_, T_, value, (long long)D_ * T_, T_,
        attnT, (long long)T_ * D_, D_, nullptr, 0, 0, nullptr, T_);

    // 5) hT[b,t,h] = relu(W1[h,:] . attnT[b,t,:] + b1[h])  (3-pass, transposed out)
    mgemm<3,2,true,2><<<dim3(8, 16, B_), 256, SM3>>>(
        W1, 0, D_, attnT, (long long)T_ * D_, D_,
        nullptr, 0, 0, hT, (long long)T_ * H_, H_, b1, D_);

    // 6) rep_in[b,d,t] = W2[d,:] . hT[b,t,:] + b2[d]  (3-pass), ldc=1025
    mgemm<3,2,false,0><<<dim3(8, 8, B_), 256, SM3>>>(
        W2, 0, H_, hT, (long long)T_ * H_, H_,
        rep, (long long)D_ * 1025, 1025, nullptr, 0, 0, b2, H_);

    // 7) ex branch: uniform attention => row-mean of value, tiny MLP
    meanv_k<<<4096, 256>>>(value, mv);
    hex_k<<<8192, 256>>>(W1, b1, mv, hx);
    yex_k<<<4096, 256>>>(W2, b2, hx, rep);
}

// round 13
// speedup vs baseline: 1.0283x; 1.0012x over previous
#include <cuda_runtime.h>
#include <cuda_bf16.h>
#include <cstdint>

#define B_  32
#define D_  1024
#define T_  1024
#define H_  2048

// ---------------- scratch (device globals; allocation forbidden) ------------
__device__ float g_scores[(size_t)B_ * T_ * T_];   // qk then softmax (in place)
__device__ float g_qT   [(size_t)T_ * B_ * D_];    // [f][b*D+d]
__device__ float g_kT   [(size_t)T_ * B_ * D_];    // [f][b*D+d]
__device__ float g_attnT[(size_t)B_ * T_ * D_];    // [b][t][d]
__device__ float g_hT   [(size_t)B_ * T_ * H_];    // [b][t][h]
__device__ float g_meanv[B_ * D_];
__device__ float g_hex  [B_ * H_];

// ---------------- helpers ----------------------------------------------------
__device__ __forceinline__ uint32_t smem_u32(const void* p) {
    uint32_t a;
    asm("{ .reg .u64 t; cvta.to.shared.u64 t, %1; cvt.u32.u64 %0, t; }"
        : "=r"(a) : "l"(p));
    return a;
}

__device__ __forceinline__ void ldsm4(uint32_t* r, uint32_t a) {
    asm volatile("ldmatrix.sync.aligned.m8n8.x4.shared.b16 {%0,%1,%2,%3}, [%4];"
        : "=r"(r[0]), "=r"(r[1]), "=r"(r[2]), "=r"(r[3]) : "r"(a));
}
__device__ __forceinline__ void ldsm2(uint32_t* r, uint32_t a) {
    asm volatile("ldmatrix.sync.aligned.m8n8.x2.shared.b16 {%0,%1}, [%2];"
        : "=r"(r[0]), "=r"(r[1]) : "r"(a));
}
__device__ __forceinline__ void mma16816(float* c, const uint32_t* a, const uint32_t* b) {
    asm volatile(
        "mma.sync.aligned.m16n8k16.row.col.f32.bf16.bf16.f32 "
        "{%0,%1,%2,%3}, {%4,%5,%6,%7}, {%8,%9}, {%0,%1,%2,%3};"
        : "+f"(c[0]), "+f"(c[1]), "+f"(c[2]), "+f"(c[3])
        : "r"(a[0]), "r"(a[1]), "r"(a[2]), "r"(a[3]), "r"(b[0]), "r"(b[1]));
}

__device__ __forceinline__ uint32_t pack_bf2(__nv_bfloat16 a, __nv_bfloat16 b) {
    __nv_bfloat162 t = __halves2bfloat162(a, b);
    return *reinterpret_cast<uint32_t*>(&t);
}

// split fp32x4 -> bf16 h/m(/l) tiles at tbase, tbase+TILE, (tbase+2*TILE)
template<int NT>
__device__ __forceinline__ void split_store(char* tbase, uint32_t off, float4 v) {
    float f[4] = {v.x, v.y, v.z, v.w};
    uint32_t hw[2], mw[2], lw[2];
#pragma unroll
    for (int p = 0; p < 2; ++p) {
        __nv_bfloat16 h0 = __float2bfloat16_rn(f[2*p]);
        __nv_bfloat16 h1 = __float2bfloat16_rn(f[2*p+1]);
        float r0 = f[2*p]   - __bfloat162float(h0);
        float r1 = f[2*p+1] - __bfloat162float(h1);
        __nv_bfloat16 m0 = __float2bfloat16_rn(r0);
        __nv_bfloat16 m1 = __float2bfloat16_rn(r1);
        hw[p] = pack_bf2(h0, h1);
        mw[p] = pack_bf2(m0, m1);
        if (NT == 3) {
            r0 -= __bfloat162float(m0);
            r1 -= __bfloat162float(m1);
            lw[p] = pack_bf2(__float2bfloat16_rn(r0), __float2bfloat16_rn(r1));
        }
    }
    *(uint2*)(tbase + off)         = make_uint2(hw[0], hw[1]);
    *(uint2*)(tbase + 10240 + off) = make_uint2(mw[0], mw[1]);
    if (NT == 3)
        *(uint2*)(tbase + 20480 + off) = make_uint2(lw[0], lw[1]);
}

// ---------------------------------------------------------------------------
// mma.sync split GEMM: C[m,n] = sum_k A[m,k]*B[n,k] (+bias)(+relu)
// A [M,K] k-major (lda), B [N,K] k-major (ldb). Tile 128x128, BK=32 fp32.
// PASSES: 3 (h,m split ~2^-18) or 6 (h,m,l split ~2^-23).
// OUTT: 0 natural only, 1 both, 2 transposed only. CT[n][m] leading dim ldt.
// BIAS: 0 none, 1 over n, 2 over m.
// smem tile: 128 rows x 80B (32 bf16 data + pad) -> conflict-free ldmatrix.
// ---------------------------------------------------------------------------
template<int PASSES, int BIAS, bool RELU, int OUTT>
__global__ __launch_bounds__(256, 2)
void mgemm(const float* __restrict__ A, long long sA, int lda,
           const float* __restrict__ Bp, long long sB, int ldb,
           float* __restrict__ C, long long sC, int ldc,
           float* __restrict__ CT, long long sCT, int ldt,
           const float* __restrict__ bias, int Kdim)
{
    constexpr int NT   = (PASSES == 6) ? 3 : 2;
    constexpr int TILE = 10240;                 // 128 * 80 bytes
    extern __shared__ char sm[];
    char* smA = sm;
    char* smB = sm + NT * TILE;
    const uint32_t uA = smem_u32(smA);
    const uint32_t uB = smem_u32(smB);

    const int tid = threadIdx.x, lane = tid & 31, wid = tid >> 5;
    const int wm = wid & 1, wn = wid >> 1;      // warp grid 2(m) x 4(n)
    const int m0 = blockIdx.y * 128, n0 = blockIdx.x * 128, z = blockIdx.z;
    const float* Ab = A  + (size_t)z * sA;
    const float* Bb = Bp + (size_t)z * sB;

    float acc[4][4][4];
#pragma unroll
    for (int i = 0; i < 4; ++i)
#pragma unroll
        for (int j = 0; j < 4; ++j)
#pragma unroll
            for (int c = 0; c < 4; ++c) acc[i][j][c] = 0.f;

    const int r8 = tid >> 3;                    // 0..31
    const int c4 = (tid & 7) << 2;              // fp32 col 0,4,..,28

    // per-thread ldmatrix row addresses
    const uint32_t aRow = (uint32_t)((wm * 64 + (lane & 15)) * 80 + (lane >> 4) * 16);
    const uint32_t bRow = (uint32_t)((wn * 32 + (lane & 7)) * 80 + ((lane >> 3) & 1) * 16);

    // pass -> (A tile, B tile); first 3 entries are the 3-pass schedule
    constexpr int PA[6] = {0, 0, 1, 0, 2, 1};
    constexpr int PB[6] = {0, 1, 0, 2, 0, 1};

    for (int k0 = 0; k0 < Kdim; k0 += 32) {
#pragma unroll
        for (int i = 0; i < 4; ++i) {
            const int row = i * 32 + r8;
            const uint32_t off = (uint32_t)(row * 80 + c4 * 2);
            float4 va = *(const float4*)(Ab + (size_t)(m0 + row) * lda + k0 + c4);
            split_store<NT>(smA, off, va);
            float4 vb = *(const float4*)(Bb + (size_t)(n0 + row) * ldb + k0 + c4);
            split_store<NT>(smB, off, vb);
        }
        __syncthreads();

#pragma unroll
        for (int p = 0; p < PASSES; ++p) {
            const uint32_t aBase = uA + PA[p] * TILE + aRow;
            const uint32_t bBase = uB + PB[p] * TILE + bRow;
#pragma unroll
            for (int ks = 0; ks < 2; ++ks) {
                uint32_t af[4][4], bf[4][2];
#pragma unroll
                for (int mt = 0; mt < 4; ++mt)
                    ldsm4(af[mt], aBase + mt * (16 * 80) + ks * 32);
#pragma unroll
                for (int nt = 0; nt < 4; ++nt)
                    ldsm2(bf[nt], bBase + nt * (8 * 80) + ks * 32);
#pragma unroll
                for (int mt = 0; mt < 4; ++mt)
#pragma unroll
                    for (int nt = 0; nt < 4; ++nt)
                        mma16816(acc[mt][nt], af[mt], bf[nt]);
            }
        }
        __syncthreads();
    }

    // ---- epilogue (direct from fragments) ----
    const int mBase = m0 + wm * 64;
    const int nBase = n0 + wn * 32;
    const int rq = lane >> 2;          // 0..7
    const int cq = (lane & 3) * 2;     // 0,2,4,6

    if (OUTT != 2) {
        float* Cb = C + (size_t)z * sC;
#pragma unroll
        for (int mt = 0; mt < 4; ++mt) {
#pragma unroll
            for (int nt = 0; nt < 4; ++nt) {
                const int m = mBase + mt * 16 + rq;
                const int n = nBase + nt * 8 + cq;
                float x0 = acc[mt][nt][0], x1 = acc[mt][nt][1];
                float x2 = acc[mt][nt][2], x3 = acc[mt][nt][3];
                if (BIAS == 1) {
                    float b0 = bias[n], b1 = bias[n + 1];
                    x0 += b0; x1 += b1; x2 += b0; x3 += b1;
                }
                if (BIAS == 2) {
                    float bm0 = bias[m], bm1 = bias[m + 8];
                    x0 += bm0; x1 += bm0; x2 += bm1; x3 += bm1;
                }
                if (RELU) {
                    x0 = fmaxf(x0, 0.f); x1 = fmaxf(x1, 0.f);
                    x2 = fmaxf(x2, 0.f); x3 = fmaxf(x3, 0.f);
                }
                if ((ldc & 1) == 0) {
                    *(float2*)(Cb + (size_t)m * ldc + n)       = make_float2(x0, x1);
                    *(float2*)(Cb + (size_t)(m + 8) * ldc + n) = make_float2(x2, x3);
                } else {
                    Cb[(size_t)m * ldc + n]           = x0;
                    Cb[(size_t)m * ldc + n + 1]       = x1;
                    Cb[(size_t)(m + 8) * ldc + n]     = x2;
                    Cb[(size_t)(m + 8) * ldc + n + 1] = x3;
                }
            }
        }
    }

    if (OUTT != 0) {
        float* Tb = CT + (size_t)z * sCT;
#pragma unroll
        for (int mt = 0; mt < 4; ++mt) {
#pragma unroll
            for (int nt = 0; nt < 4; ++nt) {
                const int m = mBase + mt * 16 + rq;
                const int n = nBase + nt * 8 + cq;
                float x0 = acc[mt][nt][0], x1 = acc[mt][nt][1];
                float x2 = acc[mt][nt][2], x3 = acc[mt][nt][3];
                if (BIAS == 1) {
                    float b0 = bias[n], b1 = bias[n + 1];
                    x0 += b0; x1 += b1; x2 += b0; x3 += b1;
                }
                if (BIAS == 2) {
                    float bm0 = bias[m], bm1 = bias[m + 8];
                    x0 += bm0; x1 += bm0; x2 += bm1; x3 += bm1;
                }
                if (RELU) {
                    x0 = fmaxf(x0, 0.f); x1 = fmaxf(x1, 0.f);
                    x2 = fmaxf(x2, 0.f); x3 = fmaxf(x3, 0.f);
                }
                Tb[(size_t)n * ldt + m]           = x0;
                Tb[(size_t)(n + 1) * ldt + m]     = x1;
                Tb[(size_t)n * ldt + m + 8]       = x2;
                Tb[(size_t)(n + 1) * ldt + m + 8] = x3;
            }
        }
    }
}

// ---------------------------------------------------------------------------
// Double-exp softmax, exactly mirroring JAX (in place)
// ---------------------------------------------------------------------------
__global__ void softmax_dexp(float* __restrict__ S)
{
    const int i = blockIdx.x;
    float* row = S + ((size_t)blockIdx.y * T_ + i) * T_;
    __shared__ float buf[T_];
    __shared__ float red[9];
    const int tid = threadIdx.x;  // 256

    float lmax = -3.402823466e38f;
    for (int j = tid; j < T_; j += 256) {
        float x = row[j];
        if (j == i) x *= 0.96875f;   // 1 - 1/sqrt(1024), exact
        float e = expf(x);
        buf[j] = e;
        lmax = fmaxf(lmax, e);
    }
#pragma unroll
    for (int o = 16; o; o >>= 1) lmax = fmaxf(lmax, __shfl_xor_sync(0xffffffffu, lmax, o));
    if ((tid & 31) == 0) red[tid >> 5] = lmax;
    __syncthreads();
    if (tid == 0) {
        float m = red[0];
        for (int s = 1; s < 8; ++s) m = fmaxf(m, red[s]);
        red[8] = m;
    }
    __syncthreads();
    const float M = red[8];

    float ls = 0.f;
    for (int j = tid; j < T_; j += 256) {
        float t = expf(buf[j] - M);
        buf[j] = t;
        ls += t;
    }
#pragma unroll
    for (int o = 16; o; o >>= 1) ls += __shfl_xor_sync(0xffffffffu, ls, o);
    if ((tid & 31) == 0) red[tid >> 5] = ls;
    __syncthreads();
    if (tid == 0) {
        float s = 0.f;
        for (int t = 0; t < 8; ++t) s += red[t];
        red[8] = 1.0f / s;
    }
    __syncthreads();
    const float inv = red[8];
    for (int j = tid; j < T_; j += 256) row[j] = buf[j] * inv;
}

// ---------------------------------------------------------------------------
__device__ __forceinline__ float warp_sum(float v)
{
#pragma unroll
    for (int o = 16; o; o >>= 1) v += __shfl_xor_sync(0xffffffffu, v, o);
    return v;
}

__global__ void meanv_k(const float* __restrict__ V, float* __restrict__ out)
{
    const int w = (blockIdx.x * blockDim.x + threadIdx.x) >> 5;
    const int lane = threadIdx.x & 31;
    if (w >= B_ * D_) return;
    const float* r = V + (size_t)w * T_;
    float s = 0.f;
    for (int j = 25 + lane; j < 1023; j += 32) s += r[j];
    s = warp_sum(s);
    if (lane == 0) out[w] = s * (1.0f / 998.0f);
}

__global__ void hex_k(const float* __restrict__ W1, const float* __restrict__ b1,
                      const float* __restrict__ mv, float* __restrict__ hx)
{
    const int w = (blockIdx.x * blockDim.x + threadIdx.x) >> 5;
    const int lane = threadIdx.x & 31;
    if (w >= B_ * H_) return;
    const int b = w >> 11, h = w & (H_ - 1);
    const float* wr = W1 + (size_t)h * D_;
    const float* xr = mv + (size_t)b * D_;
    float s = 0.f;
    for (int d = lane; d < D_; d += 32) s += wr[d] * xr[d];
    s = warp_sum(s);
    if (lane == 0) hx[w] = fmaxf(s + b1[h], 0.f);
}

__global__ void yex_k(const float* __restrict__ W2, const float* __restrict__ b2,
                      const float* __restrict__ hx, float* __restrict__ rep)
{
    const int w = (blockIdx.x * blockDim.x + threadIdx.x) >> 5;
    const int lane = threadIdx.x & 31;
    if (w >= B_ * D_) return;
    const int b = w >> 10, d = w & (D_ - 1);
    const float* wr = W2 + (size_t)d * H_;
    const float* xr = hx + (size_t)b * H_;
    float s = 0.f;
    for (int h = lane; h < H_; h += 32) s += wr[h] * xr[h];
    s = warp_sum(s);
    if (lane == 0) rep[((size_t)b * D_ + d) * 1025 + 1024] = s + b2[d];
}

// ---------------------------------------------------------------------------
extern "C" void kernel_launch(void* const* d_in, const int* in_sizes, int n_in,
                              void* d_out, int out_size)
{
    const float* pattern = (const float*)d_in[0];
    const float* value   = (const float*)d_in[1];
    const float* Wq      = (const float*)d_in[2];
    const float* bq      = (const float*)d_in[3];
    const float* Wk      = (const float*)d_in[4];
    const float* bk      = (const float*)d_in[5];
    const float* W1      = (const float*)d_in[6];
    const float* b1      = (const float*)d_in[7];
    const float* W2      = (const float*)d_in[8];
    const float* b2      = (const float*)d_in[9];

    float* out = (float*)d_out;
    float* rep = out;                                   // (B, D, 1025)
    float* q   = out + (size_t)B_ * D_ * 1025;          // (B, D, T)
    float* k   = q   + (size_t)B_ * D_ * T_;            // (B, D, T)

    float *scores, *qT, *kT, *attnT, *hT, *mv, *hx;
    cudaGetSymbolAddress((void**)&scores, g_scores);
    cudaGetSymbolAddress((void**)&qT,     g_qT);
    cudaGetSymbolAddress((void**)&kT,     g_kT);
    cudaGetSymbolAddress((void**)&attnT,  g_attnT);
    cudaGetSymbolAddress((void**)&hT,     g_hT);
    cudaGetSymbolAddress((void**)&mv,     g_meanv);
    cudaGetSymbolAddress((void**)&hx,     g_hex);

    const int SM6 = 6 * 10240;   // 61440
    const int SM3 = 4 * 10240;   // 40960
    cudaFuncSetAttribute(mgemm<6,1,false,1>, cudaFuncAttributeMaxDynamicSharedMemorySize, SM6);
    cudaFuncSetAttribute(mgemm<6,0,false,0>, cudaFuncAttributeMaxDynamicSharedMemorySize, SM6);
    cudaFuncSetAttribute(mgemm<3,0,false,0>, cudaFuncAttributeMaxDynamicSharedMemorySize, SM3);
    cudaFuncSetAttribute(mgemm<3,2,true ,2>, cudaFuncAttributeMaxDynamicSharedMemorySize, SM3);
    cudaFuncSetAttribute(mgemm<3,2,false,0>, cudaFuncAttributeMaxDynamicSharedMemorySize, SM3);

    // 1) q/k projections (6-pass): natural into d_out + transposed scratch
    //    M=32768 (b*D+d), N=1024 (f), K=1024 (t)
    mgemm<6,1,false,1><<<dim3(8, 256, 1), 256, SM6>>>(
        pattern, 0, T_, Wq, 0, T_, q, 0, T_, qT, 0, B_ * D_, bq, T_);
    mgemm<6,1,false,1><<<dim3(8, 256, 1), 256, SM6>>>(
        pattern, 0, T_, Wk, 0, T_, k, 0, T_, kT, 0, B_ * D_, bk, T_);

    // 2) qk[b,i,j] = sum_d qT[i][bD+d] * kT[j][bD+d]  (6-pass, batched)
    mgemm<6,0,false,0><<<dim3(8, 8, B_), 256, SM6>>>(
        qT, D_, B_ * D_, kT, D_, B_ * D_,
        scores, (long long)T_ * T_, T_, nullptr, 0, 0, nullptr, D_);

    // 3) double-exp softmax (in place)
    softmax_dexp<<<dim3(T_, B_), 256>>>(scores);

    // 4) attnT[b,t,d] = sum_j scores[b,t,j] * value[b,d,j]  (3-pass, natural out)
    mgemm<3,0,false,0><<<dim3(8, 8, B_), 256, SM3>>>(
        scores, (long long)T_ * T_, T_, value, (long long)D_ * T_, T_,
        attnT, (long long)T_ * D_, D_, nullptr, 0, 0, nullptr, T_);

    // 5) hT[b,t,h] = relu(W1[h,:] . attnT[b,t,:] + b1[h])  (3-pass, transposed out)
    mgemm<3,2,true,2><<<dim3(8, 16, B_), 256, SM3>>>(
        W1, 0, D_, attnT, (long long)T_ * D_, D_,
        nullptr, 0, 0, hT, (long long)T_ * H_, H_, b1, D_);

    // 6) rep_in[b,d,t] = W2[d,:] . hT[b,t,:] + b2[d]  (3-pass), ldc=1025
    mgemm<3,2,false,0><<<dim3(8, 8, B_), 256, SM3>>>(
        W2, 0, H_, hT, (long long)T_ * H_, H_,
        rep, (long long)D_ * 1025, 1025, nullptr, 0, 0, b2, H_);

    // 7) ex branch: uniform attention => row-mean of value, tiny MLP
    meanv_k<<<4096, 256>>>(value, mv);
    hex_k<<<8192, 256>>>(W1, b1, mv, hx);
    yex_k<<<4096, 256>>>(W2, b2, hx, rep);
}

// round 14
// speedup vs baseline: 1.0284x; 1.0000x over previous
#include <cuda_runtime.h>
#include <cuda_bf16.h>
#include <cstdint>

#define B_  32
#define D_  1024
#define T_  1024
#define H_  2048

// ---------------- scratch (device globals; allocation forbidden) ------------
__device__ float g_scores[(size_t)B_ * T_ * T_];   // qk then softmax (in place)
__device__ float g_qT   [(size_t)T_ * B_ * D_];    // [f][b*D+d]
__device__ float g_kT   [(size_t)T_ * B_ * D_];    // [f][b*D+d]
__device__ float g_attnT[(size_t)B_ * T_ * D_];    // [b][t][d]
__device__ float g_hT   [(size_t)B_ * T_ * H_];    // [b][t][h]
__device__ float g_meanv[B_ * D_];
__device__ float g_hex  [B_ * H_];

// ---------------- helpers ----------------------------------------------------
__device__ __forceinline__ uint32_t smem_u32(const void* p) {
    uint32_t a;
    asm("{ .reg .u64 t; cvta.to.shared.u64 t, %1; cvt.u32.u64 %0, t; }"
        : "=r"(a) : "l"(p));
    return a;
}

__device__ __forceinline__ void ldsm4(uint32_t* r, uint32_t a) {
    asm volatile("ldmatrix.sync.aligned.m8n8.x4.shared.b16 {%0,%1,%2,%3}, [%4];"
        : "=r"(r[0]), "=r"(r[1]), "=r"(r[2]), "=r"(r[3]) : "r"(a));
}
__device__ __forceinline__ void ldsm2(uint32_t* r, uint32_t a) {
    asm volatile("ldmatrix.sync.aligned.m8n8.x2.shared.b16 {%0,%1}, [%2];"
        : "=r"(r[0]), "=r"(r[1]) : "r"(a));
}
__device__ __forceinline__ void mma16816(float* c, const uint32_t* a, const uint32_t* b) {
    asm volatile(
        "mma.sync.aligned.m16n8k16.row.col.f32.bf16.bf16.f32 "
        "{%0,%1,%2,%3}, {%4,%5,%6,%7}, {%8,%9}, {%0,%1,%2,%3};"
        : "+f"(c[0]), "+f"(c[1]), "+f"(c[2]), "+f"(c[3])
        : "r"(a[0]), "r"(a[1]), "r"(a[2]), "r"(a[3]), "r"(b[0]), "r"(b[1]));
}

__device__ __forceinline__ uint32_t pack_bf2(__nv_bfloat16 a, __nv_bfloat16 b) {
    __nv_bfloat162 t = __halves2bfloat162(a, b);
    return *reinterpret_cast<uint32_t*>(&t);
}

// split fp32x4 -> bf16 h/m(/l) tiles at tbase, tbase+TILE, (tbase+2*TILE)
template<int NT>
__device__ __forceinline__ void split_store(char* tbase, uint32_t off, float4 v) {
    float f[4] = {v.x, v.y, v.z, v.w};
    uint32_t hw[2], mw[2], lw[2];
#pragma unroll
    for (int p = 0; p < 2; ++p) {
        __nv_bfloat16 h0 = __float2bfloat16_rn(f[2*p]);
        __nv_bfloat16 h1 = __float2bfloat16_rn(f[2*p+1]);
        float r0 = f[2*p]   - __bfloat162float(h0);
        float r1 = f[2*p+1] - __bfloat162float(h1);
        __nv_bfloat16 m0 = __float2bfloat16_rn(r0);
        __nv_bfloat16 m1 = __float2bfloat16_rn(r1);
        hw[p] = pack_bf2(h0, h1);
        mw[p] = pack_bf2(m0, m1);
        if (NT == 3) {
            r0 -= __bfloat162float(m0);
            r1 -= __bfloat162float(m1);
            lw[p] = pack_bf2(__float2bfloat16_rn(r0), __float2bfloat16_rn(r1));
        }
    }
    *(uint2*)(tbase + off)         = make_uint2(hw[0], hw[1]);
    *(uint2*)(tbase + 10240 + off) = make_uint2(mw[0], mw[1]);
    if (NT == 3)
        *(uint2*)(tbase + 20480 + off) = make_uint2(lw[0], lw[1]);
}

// ---------------------------------------------------------------------------
// mma.sync split GEMM: C[m,n] = sum_k A[m,k]*B[n,k] (+bias)(+relu)
// A [M,K] k-major (lda), B [N,K] k-major (ldb). Tile 128x128, BK=32 fp32.
// PASSES: 3 (h,m split ~2^-18) or 6 (h,m,l split ~2^-23).
// OUTT: 0 natural only, 1 both, 2 transposed only. CT[n][m] leading dim ldt.
// BIAS: 0 none, 1 over n, 2 over m.
// smem tile: 128 rows x 80B (32 bf16 data + pad) -> conflict-free ldmatrix.
// ---------------------------------------------------------------------------
template<int PASSES, int BIAS, bool RELU, int OUTT>
__global__ __launch_bounds__(256, 2)
void mgemm(const float* __restrict__ A, long long sA, int lda,
           const float* __restrict__ Bp, long long sB, int ldb,
           float* __restrict__ C, long long sC, int ldc,
           float* __restrict__ CT, long long sCT, int ldt,
           const float* __restrict__ bias, int Kdim)
{
    constexpr int NT   = (PASSES == 6) ? 3 : 2;
    constexpr int TILE = 10240;                 // 128 * 80 bytes
    extern __shared__ char sm[];
    char* smA = sm;
    char* smB = sm + NT * TILE;
    const uint32_t uA = smem_u32(smA);
    const uint32_t uB = smem_u32(smB);

    const int tid = threadIdx.x, lane = tid & 31, wid = tid >> 5;
    const int wm = wid & 1, wn = wid >> 1;      // warp grid 2(m) x 4(n)
    const int m0 = blockIdx.y * 128, n0 = blockIdx.x * 128, z = blockIdx.z;
    const float* Ab = A  + (size_t)z * sA;
    const float* Bb = Bp + (size_t)z * sB;

    float acc[4][4][4];
#pragma unroll
    for (int i = 0; i < 4; ++i)
#pragma unroll
        for (int j = 0; j < 4; ++j)
#pragma unroll
            for (int c = 0; c < 4; ++c) acc[i][j][c] = 0.f;

    const int r8 = tid >> 3;                    // 0..31
    const int c4 = (tid & 7) << 2;              // fp32 col 0,4,..,28

    // per-thread ldmatrix row addresses
    const uint32_t aRow = (uint32_t)((wm * 64 + (lane & 15)) * 80 + (lane >> 4) * 16);
    const uint32_t bRow = (uint32_t)((wn * 32 + (lane & 7)) * 80 + ((lane >> 3) & 1) * 16);

    // pass -> (A tile, B tile); first 3 entries are the 3-pass schedule
    constexpr int PA[6] = {0, 0, 1, 0, 2, 1};
    constexpr int PB[6] = {0, 1, 0, 2, 0, 1};

    for (int k0 = 0; k0 < Kdim; k0 += 32) {
#pragma unroll
        for (int i = 0; i < 4; ++i) {
            const int row = i * 32 + r8;
            const uint32_t off = (uint32_t)(row * 80 + c4 * 2);
            float4 va = *(const float4*)(Ab + (size_t)(m0 + row) * lda + k0 + c4);
            split_store<NT>(smA, off, va);
            float4 vb = *(const float4*)(Bb + (size_t)(n0 + row) * ldb + k0 + c4);
            split_store<NT>(smB, off, vb);
        }
        __syncthreads();

#pragma unroll
        for (int p = 0; p < PASSES; ++p) {
            const uint32_t aBase = uA + PA[p] * TILE + aRow;
            const uint32_t bBase = uB + PB[p] * TILE + bRow;
#pragma unroll
            for (int ks = 0; ks < 2; ++ks) {
                uint32_t af[4][4], bf[4][2];
#pragma unroll
                for (int mt = 0; mt < 4; ++mt)
                    ldsm4(af[mt], aBase + mt * (16 * 80) + ks * 32);
#pragma unroll
                for (int nt = 0; nt < 4; ++nt)
                    ldsm2(bf[nt], bBase + nt * (8 * 80) + ks * 32);
#pragma unroll
                for (int mt = 0; mt < 4; ++mt)
#pragma unroll
                    for (int nt = 0; nt < 4; ++nt)
                        mma16816(acc[mt][nt], af[mt], bf[nt]);
            }
        }
        __syncthreads();
    }

    // ---- epilogue (direct from fragments) ----
    const int mBase = m0 + wm * 64;
    const int nBase = n0 + wn * 32;
    const int rq = lane >> 2;          // 0..7
    const int cq = (lane & 3) * 2;     // 0,2,4,6

    if (OUTT != 2) {
        float* Cb = C + (size_t)z * sC;
#pragma unroll
        for (int mt = 0; mt < 4; ++mt) {
#pragma unroll
            for (int nt = 0; nt < 4; ++nt) {
                const int m = mBase + mt * 16 + rq;
                const int n = nBase + nt * 8 + cq;
                float x0 = acc[mt][nt][0], x1 = acc[mt][nt][1];
                float x2 = acc[mt][nt][2], x3 = acc[mt][nt][3];
                if (BIAS == 1) {
                    float b0 = bias[n], b1 = bias[n + 1];
                    x0 += b0; x1 += b1; x2 += b0; x3 += b1;
                }
                if (BIAS == 2) {
                    float bm0 = bias[m], bm1 = bias[m + 8];
                    x0 += bm0; x1 += bm0; x2 += bm1; x3 += bm1;
                }
                if (RELU) {
                    x0 = fmaxf(x0, 0.f); x1 = fmaxf(x1, 0.f);
                    x2 = fmaxf(x2, 0.f); x3 = fmaxf(x3, 0.f);
                }
                if ((ldc & 1) == 0) {
                    *(float2*)(Cb + (size_t)m * ldc + n)       = make_float2(x0, x1);
                    *(float2*)(Cb + (size_t)(m + 8) * ldc + n) = make_float2(x2, x3);
                } else {
                    Cb[(size_t)m * ldc + n]           = x0;
                    Cb[(size_t)m * ldc + n + 1]       = x1;
                    Cb[(size_t)(m + 8) * ldc + n]     = x2;
                    Cb[(size_t)(m + 8) * ldc + n + 1] = x3;
                }
            }
        }
    }

    if (OUTT != 0) {
        float* Tb = CT + (size_t)z * sCT;
#pragma unroll
        for (int mt = 0; mt < 4; ++mt) {
#pragma unroll
            for (int nt = 0; nt < 4; ++nt) {
                const int m = mBase + mt * 16 + rq;
                const int n = nBase + nt * 8 + cq;
                float x0 = acc[mt][nt][0], x1 = acc[mt][nt][1];
                float x2 = acc[mt][nt][2], x3 = acc[mt][nt][3];
                if (BIAS == 1) {
                    float b0 = bias[n], b1 = bias[n + 1];
                    x0 += b0; x1 += b1; x2 += b0; x3 += b1;
                }
                if (BIAS == 2) {
                    float bm0 = bias[m], bm1 = bias[m + 8];
                    x0 += bm0; x1 += bm0; x2 += bm1; x3 += bm1;
                }
                if (RELU) {
                    x0 = fmaxf(x0, 0.f); x1 = fmaxf(x1, 0.f);
                    x2 = fmaxf(x2, 0.f); x3 = fmaxf(x3, 0.f);
                }
                Tb[(size_t)n * ldt + m]           = x0;
                Tb[(size_t)(n + 1) * ldt + m]     = x1;
                Tb[(size_t)n * ldt + m + 8]       = x2;
                Tb[(size_t)(n + 1) * ldt + m + 8] = x3;
            }
        }
    }
}

// ---------------------------------------------------------------------------
// Double-exp softmax, exactly mirroring JAX (in place)
// ---------------------------------------------------------------------------
__global__ void softmax_dexp(float* __restrict__ S)
{
    const int i = blockIdx.x;
    float* row = S + ((size_t)blockIdx.y * T_ + i) * T_;
    __shared__ float buf[T_];
    __shared__ float red[9];
    const int tid = threadIdx.x;  // 256

    float lmax = -3.402823466e38f;
    for (int j = tid; j < T_; j += 256) {
        float x = row[j];
        if (j == i) x *= 0.96875f;   // 1 - 1/sqrt(1024), exact
        float e = expf(x);
        buf[j] = e;
        lmax = fmaxf(lmax, e);
    }
#pragma unroll
    for (int o = 16; o; o >>= 1) lmax = fmaxf(lmax, __shfl_xor_sync(0xffffffffu, lmax, o));
    if ((tid & 31) == 0) red[tid >> 5] = lmax;
    __syncthreads();
    if (tid == 0) {
        float m = red[0];
        for (int s = 1; s < 8; ++s) m = fmaxf(m, red[s]);
        red[8] = m;
    }
    __syncthreads();
    const float M = red[8];

    float ls = 0.f;
    for (int j = tid; j < T_; j += 256) {
        float t = expf(buf[j] - M);
        buf[j] = t;
        ls += t;
    }
#pragma unroll
    for (int o = 16; o; o >>= 1) ls += __shfl_xor_sync(0xffffffffu, ls, o);
    if ((tid & 31) == 0) red[tid >> 5] = ls;
    __syncthreads();
    if (tid == 0) {
        float s = 0.f;
        for (int t = 0; t < 8; ++t) s += red[t];
        red[8] = 1.0f / s;
    }
    __syncthreads();
    const float inv = red[8];
    for (int j = tid; j < T_; j += 256) row[j] = buf[j] * inv;
}

// ---------------------------------------------------------------------------
__device__ __forceinline__ float warp_sum(float v)
{
#pragma unroll
    for (int o = 16; o; o >>= 1) v += __shfl_xor_sync(0xffffffffu, v, o);
    return v;
}

__global__ void meanv_k(const float* __restrict__ V, float* __restrict__ out)
{
    const int w = (blockIdx.x * blockDim.x + threadIdx.x) >> 5;
    const int lane = threadIdx.x & 31;
    if (w >= B_ * D_) return;
    const float* r = V + (size_t)w * T_;
    float s = 0.f;
    for (int j = 25 + lane; j < 1023; j += 32) s += r[j];
    s = warp_sum(s);
    if (lane == 0) out[w] = s * (1.0f / 998.0f);
}

__global__ void hex_k(const float* __restrict__ W1, const float* __restrict__ b1,
                      const float* __restrict__ mv, float* __restrict__ hx)
{
    const int w = (blockIdx.x * blockDim.x + threadIdx.x) >> 5;
    const int lane = threadIdx.x & 31;
    if (w >= B_ * H_) return;
    const int b = w >> 11, h = w & (H_ - 1);
    const float* wr = W1 + (size_t)h * D_;
    const float* xr = mv + (size_t)b * D_;
    float s = 0.f;
    for (int d = lane; d < D_; d += 32) s += wr[d] * xr[d];
    s = warp_sum(s);
    if (lane == 0) hx[w] = fmaxf(s + b1[h], 0.f);
}

__global__ void yex_k(const float* __restrict__ W2, const float* __restrict__ b2,
                      const float* __restrict__ hx, float* __restrict__ rep)
{
    const int w = (blockIdx.x * blockDim.x + threadIdx.x) >> 5;
    const int lane = threadIdx.x & 31;
    if (w >= B_ * D_) return;
    const int b = w >> 10, d = w & (D_ - 1);
    const float* wr = W2 + (size_t)d * H_;
    const float* xr = hx + (size_t)b * H_;
    float s = 0.f;
    for (int h = lane; h < H_; h += 32) s += wr[h] * xr[h];
    s = warp_sum(s);
    if (lane == 0) rep[((size_t)b * D_ + d) * 1025 + 1024] = s + b2[d];
}

// ---------------------------------------------------------------------------
extern "C" void kernel_launch(void* const* d_in, const int* in_sizes, int n_in,
                              void* d_out, int out_size)
{
    const float* pattern = (const float*)d_in[0];
    const float* value   = (const float*)d_in[1];
    const float* Wq      = (const float*)d_in[2];
    const float* bq      = (const float*)d_in[3];
    const float* Wk      = (const float*)d_in[4];
    const float* bk      = (const float*)d_in[5];
    const float* W1      = (const float*)d_in[6];
    const float* b1      = (const float*)d_in[7];
    const float* W2      = (const float*)d_in[8];
    const float* b2      = (const float*)d_in[9];

    float* out = (float*)d_out;
    float* rep = out;                                   // (B, D, 1025)
    float* q   = out + (size_t)B_ * D_ * 1025;          // (B, D, T)
    float* k   = q   + (size_t)B_ * D_ * T_;            // (B, D, T)

    float *scores, *qT, *kT, *attnT, *hT, *mv, *hx;
    cudaGetSymbolAddress((void**)&scores, g_scores);
    cudaGetSymbolAddress((void**)&qT,     g_qT);
    cudaGetSymbolAddress((void**)&kT,     g_kT);
    cudaGetSymbolAddress((void**)&attnT,  g_attnT);
    cudaGetSymbolAddress((void**)&hT,     g_hT);
    cudaGetSymbolAddress((void**)&mv,     g_meanv);
    cudaGetSymbolAddress((void**)&hx,     g_hex);

    const int SM6 = 6 * 10240;   // 61440
    const int SM3 = 4 * 10240;   // 40960
    cudaFuncSetAttribute(mgemm<6,1,false,1>, cudaFuncAttributeMaxDynamicSharedMemorySize, SM6);
    cudaFuncSetAttribute(mgemm<6,0,false,0>, cudaFuncAttributeMaxDynamicSharedMemorySize, SM6);
    cudaFuncSetAttribute(mgemm<3,0,false,0>, cudaFuncAttributeMaxDynamicSharedMemorySize, SM3);
    cudaFuncSetAttribute(mgemm<3,2,true ,2>, cudaFuncAttributeMaxDynamicSharedMemorySize, SM3);
    cudaFuncSetAttribute(mgemm<3,2,false,0>, cudaFuncAttributeMaxDynamicSharedMemorySize, SM3);

    // 1) q/k projections (6-pass): natural into d_out + transposed scratch
    //    M=32768 (b*D+d), N=1024 (f), K=1024 (t)
    mgemm<6,1,false,1><<<dim3(8, 256, 1), 256, SM6>>>(
        pattern, 0, T_, Wq, 0, T_, q, 0, T_, qT, 0, B_ * D_, bq, T_);
    mgemm<6,1,false,1><<<dim3(8, 256, 1), 256, SM6>>>(
        pattern, 0, T_, Wk, 0, T_, k, 0, T_, kT, 0, B_ * D_, bk, T_);

    // 2) qk[b,i,j] = sum_d qT[i][bD+d] * kT[j][bD+d]  (6-pass, batched)
    mgemm<6,0,false,0><<<dim3(8, 8, B_), 256, SM6>>>(
        qT, D_, B_ * D_, kT, D_, B_ * D_,
        scores, (long long)T_ * T_, T_, nullptr, 0, 0, nullptr, D_);

    // 3) double-exp softmax (in place)
    softmax_dexp<<<dim3(T_, B_), 256>>>(scores);

    // 4) attnT[b,t,d] = sum_j scores[b,t,j] * value[b,d,j]  (3-pass, natural out)
    mgemm<3,0,false,0><<<dim3(8, 8, B_), 256, SM3>>>(
        scores, (long long)T_ * T_, T_, value, (long long)D_ * T_, T_,
        attnT, (long long)T_ * D_, D_, nullptr, 0, 0, nullptr, T_);

    // 5) hT[b,t,h] = relu(W1[h,:] . attnT[b,t,:] + b1[h])  (3-pass, transposed out)
    mgemm<3,2,true,2><<<dim3(8, 16, B_), 256, SM3>>>(
        W1, 0, D_, attnT, (long long)T_ * D_, D_,
        nullptr, 0, 0, hT, (long long)T_ * H_, H_, b1, D_);

    // 6) rep_in[b,d,t] = W2[d,:] . hT[b,t,:] + b2[d]  (3-pass), ldc=1025
    mgemm<3,2,false,0><<<dim3(8, 8, B_), 256, SM3>>>(
        W2, 0, H_, hT, (long long)T_ * H_, H_,
        rep, (long long)D_ * 1025, 1025, nullptr, 0, 0, b2, H_);

    // 7) ex branch: uniform attention => row-mean of value, tiny MLP
    meanv_k<<<4096, 256>>>(value, mv);
    hex_k<<<8192, 256>>>(W1, b1, mv, hx);
    yex_k<<<4096, 256>>>(W2, b2, hx, rep);
}